// round 17
// baseline (speedup 1.0000x reference)
#include <cuda_runtime.h>
#include <cuda_bf16.h>
#include <cstdint>

// B=16, C=128, H=W=224, KS=3, STRIDE=2, ALPHA=16 -> h[z] = -(z/t)^16; Ho=Wo=111.
#define B_  16
#define C_  128
#define H_  224
#define W_  224
#define HO_ 111
#define WO_ 111
#define TR  4                         // output rows per block
#define NROWS (2*TR + 1)              // 9 input rows
#define SEGS  (W_ / 4)                // 56 float4 segments per row
#define PITCH 228                     // smem floats per row (224 + 4 pad)

__global__ __launch_bounds__(64)
void lfp_kernel(const float* __restrict__ f,
                const float* __restrict__ t,
                float* __restrict__ out)
{
    __shared__ float s[NROWS][PITCH];            // 9*228*4 = 8208 B

    const int tid = threadIdx.x;                 // 0..63
    const int bc  = blockIdx.y;                  // b*C + c
    const int c   = bc & (C_ - 1);

    // h0 = 0, h1 = -(1/t)^16, h2 = -(2/t)^16
    const float inv = 1.0f / __ldg(t + c);
    const float x2  = inv * inv;
    const float x4  = x2 * x2;
    const float x8  = x4 * x4;
    const float x16 = x8 * x8;
    const float h1  = -x16;
    const float h2  = -65536.0f * x16;

    const float* __restrict__ fb = f + (size_t)bc * (H_ * W_);
    float* __restrict__ ob = out + (size_t)bc * (HO_ * WO_);

    const int i0 = blockIdx.x * TR;              // first output row
    const int r0 = 2 * i0;                       // first input row (even)

    // ---- Phase 1: cp.async the 9-row tile into smem (no register residency) ----
    const unsigned sbase = (unsigned)__cvta_generic_to_shared(&s[0][0]);
    #pragma unroll
    for (int it = 0; it < 8; ++it) {
        const int idx = tid + 64 * it;           // 0..511; 504 real segments
        const int r   = idx / SEGS;
        const int seg = idx - r * SEGS;
        int gr = r0 + r;
        if (gr > H_ - 1) gr = H_ - 1;            // clamp; clamped rows never used
        const float* src = fb + (size_t)gr * W_ + 4 * seg;
        const unsigned dst = sbase + (unsigned)(r * PITCH + 4 * seg) * 4u;
        if (idx < NROWS * SEGS) {
            asm volatile("cp.async.cg.shared.global [%0], [%1], 16;\n"
                         :: "r"(dst), "l"(src));
        }
    }
    asm volatile("cp.async.commit_group;\n");
    asm volatile("cp.async.wait_group 0;\n" ::: "memory");
    __syncthreads();

    // ---- Phase 2: fold rows from smem into running output maxes ----
    // Row parity fixes the kernel role: odd rows = middle, even rows = top/bottom.
    //   odd  r: w = max(center,      edge + h1)
    //   even r: w = max(center + h1, edge + h2)
    // Thread k owns output cols ja=2k (center=q.y, edge=max(q.x,q.z))
    //                       and jb=2k+1 (center=q.w, edge=max(q.z, s[r][4k+4]))
    const int k = (tid < 56) ? tid : 55;

    float oa[TR], obv[TR];
    #pragma unroll
    for (int ii = 0; ii < TR; ++ii) { oa[ii] = -__builtin_huge_valf(); obv[ii] = -__builtin_huge_valf(); }

    #pragma unroll
    for (int p = 0; p < NROWS; ++p) {
        const float4 q  = *(const float4*)&s[p][4 * k];
        const float  nx = s[p][4 * k + 4];       // k=55 -> pad (never stored)
        const float ca = q.y, ea = fmaxf(q.x, q.z);
        const float cb = q.w, eb = fmaxf(q.z, nx);
        float wa_, wb_;
        if (p & 1) { wa_ = fmaxf(ca,      ea + h1); wb_ = fmaxf(cb,      eb + h1); }
        else       { wa_ = fmaxf(ca + h1, ea + h2); wb_ = fmaxf(cb + h1, eb + h2); }
        #pragma unroll
        for (int ii = 0; ii < TR; ++ii) {
            if (p >= 2 * ii && p <= 2 * ii + 2) {
                oa[ii]  = fmaxf(oa[ii],  wa_);
                obv[ii] = fmaxf(obv[ii], wb_);
            }
        }
    }

    // ---- Phase 3: stores ----
    const int ja = 2 * k;                        // 0..110
    const int jb = ja + 1;                       // 1..111 (111 predicated off)
    const bool wa = (tid < 56);
    const bool wb = wa && (jb < WO_);

    #pragma unroll
    for (int ii = 0; ii < TR; ++ii) {
        const int i = i0 + ii;
        if (i >= HO_) break;                     // uniform per block
        float* orow = ob + (size_t)i * WO_;
        if (wa) orow[ja] = oa[ii];
        if (wb) orow[jb] = obv[ii];
    }
}

extern "C" void kernel_launch(void* const* d_in, const int* in_sizes, int n_in,
                              void* d_out, int out_size)
{
    const float* f = (const float*)d_in[0];
    const float* t = (const float*)d_in[1];
    float* out = (float*)d_out;

    dim3 block(64, 1, 1);
    dim3 grid((HO_ + TR - 1) / TR, B_ * C_, 1);   // 28 x 2048
    lfp_kernel<<<grid, block>>>(f, t, out);
}